// round 10
// baseline (speedup 1.0000x reference)
#include <cuda_runtime.h>
#include <cuda_fp16.h>
#include <cstdint>

#define BN 8192
#define CN 16
#define DN 256
#define RN 64
#define EN 32
#define ORDN 16
#define LN 32

#define MT 128    // bodies per tensor CTA
#define NH 128    // j-half per tensor CTA
#define KC 32     // tensor K chunk (two k16 mma tiles)
#define TBT 44    // tensor btiles (bodies 0 .. TBT*128-1)

#define BT 64     // bodies per scalar CTA
#define KT 32     // scalar i-tile rows

// Scratch (__device__ globals; every element written each launch)
__device__ float g_q2[BN * CN * 2];

// tensor-path smem u32 layout (first 33792 B of the 96KB block):
#define SM_DLO 2048
#define SM_BHI 4096
#define SM_BLO 6208

// ---------------------------------------------------------------------------
// helpers
// ---------------------------------------------------------------------------
__device__ __forceinline__ uint32_t pk_h2(float a, float b) {
    __half2 h = __floats2half2_rn(a, b);  // .x = first arg
    return *reinterpret_cast<uint32_t*>(&h);
}
__device__ __forceinline__ void mma_f16(float* c, uint4 a, uint2 b) {
    asm volatile(
        "mma.sync.aligned.m16n8k16.row.col.f32.f16.f16.f32 "
        "{%0,%1,%2,%3}, {%4,%5,%6,%7}, {%8,%9}, {%0,%1,%2,%3};"
        : "+f"(c[0]), "+f"(c[1]), "+f"(c[2]), "+f"(c[3])
        : "r"(a.x), "r"(a.y), "r"(a.z), "r"(a.w), "r"(b.x), "r"(b.y));
}
// packed f32x2
__device__ __forceinline__ unsigned long long pk2(float lo, float hi) {
    unsigned long long r;
    asm("mov.b64 %0, {%1, %2};" : "=l"(r) : "f"(lo), "f"(hi));
    return r;
}
__device__ __forceinline__ void upk2(unsigned long long v, float& lo, float& hi) {
    asm("mov.b64 {%0, %1}, %2;" : "=f"(lo), "=f"(hi) : "l"(v));
}
__device__ __forceinline__ unsigned long long ffma2(unsigned long long a,
                                                    unsigned long long b,
                                                    unsigned long long c) {
    unsigned long long d;
    asm("fma.rn.f32x2 %0, %1, %2, %3;" : "=l"(d) : "l"(a), "l"(b), "l"(c));
    return d;
}
__device__ __forceinline__ unsigned long long fadd2(unsigned long long a,
                                                    unsigned long long b) {
    unsigned long long d;
    asm("add.rn.f32x2 %0, %1, %2;" : "=l"(d) : "l"(a), "l"(b));
    return d;
}

// ---------------------------------------------------------------------------
// quad_hybrid_kernel: d2[b,c] = sum_j ( sum_i sig[c,i,j]*(mu[c,i]-z[b,i]) )^2
// blocks x < TBT : fp16x3 mma path (bodies x*128.., j-half nh)     [round-9]
// blocks x >= TBT: FFMA2 scalar path (64 bodies, all j)            [round-2]
// grid (64, 2, 16), 256 threads, 96KB smem, 2 CTAs/SM.
// ---------------------------------------------------------------------------
__global__ __launch_bounds__(256, 2) void quad_hybrid_kernel(
    const float* __restrict__ z, const float* __restrict__ mu,
    const float* __restrict__ sig) {
    extern __shared__ uint32_t smu[];
    const int x = blockIdx.x, nh = blockIdx.y, c = blockIdx.z;
    const int tid = threadIdx.x;
    const float* sigc = sig + (size_t)c * DN * DN;

    if (x < TBT) {
        // =================== TENSOR PATH (fp16 x3 mma) =====================
        const int b0 = x * MT, j0 = nh * NH;
        const int wid = tid >> 5, lane = tid & 31;

        float acc[16][4];
#pragma unroll
        for (int nt = 0; nt < 16; nt++)
#pragma unroll
            for (int i = 0; i < 4; i++) acc[nt][i] = 0.f;

        __half* BhiH = (__half*)(smu + SM_BHI);
        __half* BloH = (__half*)(smu + SM_BLO);

        for (int kt = 0; kt < DN / KC; kt++) {
            const int i0 = kt * KC;
            if (kt) __syncthreads();

            // stage D (A operand): d = mu - z, fp16 hi/lo, fragment order
#pragma unroll
            for (int it = 0; it < 4; it++) {
                int idx = tid + it * 256;
                int b = idx >> 3, i4 = idx & 7;
                float4 zv = *(const float4*)(z + (size_t)(b0 + b) * DN + i0 + i4 * 4);
                float4 m4 = *(const float4*)(mu + c * DN + i0 + i4 * 4);
                float v[4] = {m4.x - zv.x, m4.y - zv.y, m4.z - zv.z, m4.w - zv.w};
                __half h0 = __float2half_rn(v[0]), h1 = __float2half_rn(v[1]);
                __half h2 = __float2half_rn(v[2]), h3 = __float2half_rn(v[3]);
                float l0 = v[0] - __half2float(h0), l1 = v[1] - __half2float(h1);
                float l2 = v[2] - __half2float(h2), l3 = v[3] - __half2float(h3);
                int r = b & 15, g = r & 7, rh = r >> 3, mslot = b >> 4;
                int kt16 = i4 >> 2, sl = (i4 >> 1) & 1, t0 = (i4 & 1) * 2;
                int reg = rh + 2 * sl;
                int base = ((mslot * 2 + kt16) * 32 + g * 4 + t0) * 4 + reg;
                smu[base]              = pk_h2(__half2float(h0), __half2float(h1));
                smu[base + 4]          = pk_h2(__half2float(h2), __half2float(h3));
                smu[SM_DLO + base]     = pk_h2(l0, l1);
                smu[SM_DLO + base + 4] = pk_h2(l2, l3);
            }
            // stage B: sig K-major (k=i, n=j), fp16 hi/lo, padded rows (33)
#pragma unroll
            for (int it = 0; it < 4; it++) {
                int idx = tid + it * 256;
                int ii = idx >> 5, j4 = idx & 31;
                float4 av = *(const float4*)(sigc + (size_t)(i0 + ii) * DN + j0 + j4 * 4);
                float v[4] = {av.x, av.y, av.z, av.w};
                int kk = ii & 15, kt16 = ii >> 4;
                int t = (kk & 7) >> 1, sl = kk >> 3, hp = kk & 1;
#pragma unroll
                for (int e = 0; e < 4; e++) {
                    int jl = j4 * 4 + e;
                    int nt = jl >> 3, g = jl & 7;
                    int hidx = ((((kt16 * 16 + nt) * 33 + g * 4 + t) * 2 + sl) * 2) + hp;
                    __half h = __float2half_rn(v[e]);
                    BhiH[hidx] = h;
                    BloH[hidx] = __float2half_rn(v[e] - __half2float(h));
                }
            }
            __syncthreads();

            const uint4* Dhi4 = (const uint4*)smu;
            const uint4* Dlo4 = (const uint4*)(smu + SM_DLO);
            const uint2* Bhi2 = (const uint2*)(smu + SM_BHI);
            const uint2* Blo2 = (const uint2*)(smu + SM_BLO);
#pragma unroll
            for (int ktile = 0; ktile < 2; ktile++) {
                uint4 ah = Dhi4[(wid * 2 + ktile) * 32 + lane];
                uint4 al = Dlo4[(wid * 2 + ktile) * 32 + lane];
#pragma unroll
                for (int nt = 0; nt < 16; nt++) {
                    uint2 bh = Bhi2[(ktile * 16 + nt) * 33 + lane];
                    uint2 bl = Blo2[(ktile * 16 + nt) * 33 + lane];
                    mma_f16(acc[nt], ah, bh);
                    mma_f16(acc[nt], ah, bl);
                    mma_f16(acc[nt], al, bh);
                }
            }
        }

        // epilogue: q = sum acc^2 over this j-half
        float q0 = 0.f, q1 = 0.f;
#pragma unroll
        for (int nt = 0; nt < 16; nt++) {
            q0 += acc[nt][0] * acc[nt][0] + acc[nt][1] * acc[nt][1];
            q1 += acc[nt][2] * acc[nt][2] + acc[nt][3] * acc[nt][3];
        }
        q0 += __shfl_xor_sync(0xffffffffu, q0, 1);
        q0 += __shfl_xor_sync(0xffffffffu, q0, 2);
        q1 += __shfl_xor_sync(0xffffffffu, q1, 1);
        q1 += __shfl_xor_sync(0xffffffffu, q1, 2);
        if ((lane & 3) == 0) {
            int b = b0 + wid * 16 + (lane >> 2);
            g_q2[((size_t)b * CN + c) * 2 + nh]       = q0;
            g_q2[((size_t)(b + 8) * CN + c) * 2 + nh] = q1;
        }
    } else {
        // =================== SCALAR PATH (FFMA2) ===========================
        const int b0 = TBT * MT + ((x - TBT) * 2 + nh) * BT;
        float* Ds = (float*)smu;            // [DN][BT]: mu - z transposed
        float* As = (float*)smu + DN * BT;  // [KT][DN]
        const int tx = tid & 31;            // j group
        const int ty = tid >> 5;            // body group (warp)

        for (int idx = tid; idx < BT * (DN / 4); idx += 256) {
            int b  = idx & (BT - 1);
            int kq = idx >> 6;
            float4 zz = *(const float4*)(z + (size_t)(b0 + b) * DN + kq * 4);
            float4 mm = *(const float4*)(mu + c * DN + kq * 4);
            Ds[(kq * 4 + 0) * BT + b] = mm.x - zz.x;
            Ds[(kq * 4 + 1) * BT + b] = mm.y - zz.y;
            Ds[(kq * 4 + 2) * BT + b] = mm.z - zz.z;
            Ds[(kq * 4 + 3) * BT + b] = mm.w - zz.w;
        }

        unsigned long long v[8][4];
#pragma unroll
        for (int jj = 0; jj < 8; jj++)
#pragma unroll
            for (int bp = 0; bp < 4; bp++) v[jj][bp] = 0ull;

        for (int it = 0; it < DN; it += KT) {
            __syncthreads();
            for (int idx = tid; idx < KT * (DN / 4); idx += 256) {
                int j4 = idx & 63;
                int ii = idx >> 6;
                *(float4*)&As[ii * DN + j4 * 4] =
                    *(const float4*)(sigc + (size_t)(it + ii) * DN + j4 * 4);
            }
            __syncthreads();

#pragma unroll 4
            for (int ii = 0; ii < KT; ii++) {
                ulonglong2 za = *(const ulonglong2*)&Ds[(it + ii) * BT + ty * 8];
                ulonglong2 zb = *(const ulonglong2*)&Ds[(it + ii) * BT + ty * 8 + 4];
                unsigned long long z2[4] = {za.x, za.y, zb.x, zb.y};
                float4 a0 = *(const float4*)&As[ii * DN + tx * 4];
                float4 a1 = *(const float4*)&As[ii * DN + 128 + tx * 4];
                unsigned long long ad[8] = {
                    pk2(a0.x, a0.x), pk2(a0.y, a0.y), pk2(a0.z, a0.z), pk2(a0.w, a0.w),
                    pk2(a1.x, a1.x), pk2(a1.y, a1.y), pk2(a1.z, a1.z), pk2(a1.w, a1.w)};
#pragma unroll
                for (int jj = 0; jj < 8; jj++)
#pragma unroll
                    for (int bp = 0; bp < 4; bp++)
                        v[jj][bp] = ffma2(z2[bp], ad[jj], v[jj][bp]);
            }
        }

        unsigned long long q2[4] = {0ull, 0ull, 0ull, 0ull};
#pragma unroll
        for (int jj = 0; jj < 8; jj++)
#pragma unroll
            for (int bp = 0; bp < 4; bp++) q2[bp] = ffma2(v[jj][bp], v[jj][bp], q2[bp]);

#pragma unroll
        for (int m = 16; m; m >>= 1) {
#pragma unroll
            for (int bp = 0; bp < 4; bp++) {
                unsigned long long o = __shfl_xor_sync(0xffffffffu, q2[bp], m);
                q2[bp] = fadd2(q2[bp], o);
            }
        }
        if (tx == 0) {
#pragma unroll
            for (int bp = 0; bp < 4; bp++) {
                float lo, hi;
                upk2(q2[bp], lo, hi);
                int b = b0 + ty * 8 + bp * 2;
                g_q2[((size_t)b * CN + c) * 2]           = lo;
                g_q2[((size_t)b * CN + c) * 2 + 1]       = 0.f;
                g_q2[((size_t)(b + 1) * CN + c) * 2]     = hi;
                g_q2[((size_t)(b + 1) * CN + c) * 2 + 1] = 0.f;
            }
        }
    }
}

// ---------------------------------------------------------------------------
// Kernel B: d2 -> softmax -> ARX recursion -> weighted output.
// ---------------------------------------------------------------------------
__global__ __launch_bounds__(256) void arx_out_kernel(
    const float* __restrict__ y, const float* __restrict__ u,
    const float* __restrict__ a_coef, const float* __restrict__ b_coef,
    const float* __restrict__ bias, float* __restrict__ out) {
    __shared__ float ps[16 * 16 * 33];
    __shared__ float acs[CN * ORDN];
    __shared__ float bcs[CN * EN];
    __shared__ float bss[CN];

    const int tid = threadIdx.x;
    if (tid < CN * ORDN) acs[tid] = a_coef[tid];
    for (int i = tid; i < CN * EN; i += 256) bcs[i] = b_coef[i];
    if (tid < CN) bss[tid] = bias[tid];
    __syncthreads();

    const int tb = tid >> 4;
    const int tc = tid & 15;
    const int b  = blockIdx.x * 16 + tb;

    float d2 = g_q2[((size_t)b * CN + tc) * 2] + g_q2[((size_t)b * CN + tc) * 2 + 1];
    d2 = fmaxf(d2, 1e-8f);

    float mn = d2;
#pragma unroll
    for (int m = 8; m; m >>= 1) mn = fminf(mn, __shfl_xor_sync(0xffffffffu, mn, m));
    float e = expf(-(d2 - mn));
    float ssum = e;
#pragma unroll
    for (int m = 8; m; m >>= 1) ssum += __shfl_xor_sync(0xffffffffu, ssum, m);
    float psi = e / ssum;

    const float4* uv = (const float4*)(u + ((size_t)b * CN + tc) * EN);
    float ub = bss[tc];
#pragma unroll
    for (int k = 0; k < EN / 4; k++) {
        float4 uu = uv[k];
        const float* bc = &bcs[tc * EN + k * 4];
        ub += uu.x * bc[0] + uu.y * bc[1] + uu.z * bc[2] + uu.w * bc[3];
    }

    float s[ORDN];
    const float4* yv = (const float4*)(y + ((size_t)b * CN + tc) * RN + (RN - ORDN));
#pragma unroll
    for (int k = 0; k < ORDN / 4; k++) {
        float4 t = yv[k];
        s[k * 4 + 0] = t.x; s[k * 4 + 1] = t.y;
        s[k * 4 + 2] = t.z; s[k * 4 + 3] = t.w;
    }
    float ar[ORDN];
#pragma unroll
    for (int o = 0; o < ORDN; o++) ar[o] = acs[tc * ORDN + o];

    float* myps = &ps[(tb * 16 + tc) * 33];
#pragma unroll
    for (int l = 0; l < LN; l++) {
        float y0 = 0.f, y1 = 0.f;
#pragma unroll
        for (int o = 0; o < ORDN; o += 2) {
            y0 += s[o] * ar[o];
            y1 += s[o + 1] * ar[o + 1];
        }
        float yn = ub + y0 + y1;
#pragma unroll
        for (int o = 0; o < ORDN - 1; o++) s[o] = s[o + 1];
        s[ORDN - 1] = yn;
        myps[l] = psi * yn;
    }
    __syncthreads();

    for (int o = tid; o < 16 * LN; o += 256) {
        int bb = o >> 5, l = o & 31;
        float acc = 0.f;
#pragma unroll
        for (int cc = 0; cc < CN; cc++) acc += ps[(bb * 16 + cc) * 33 + l];
        out[(size_t)(blockIdx.x * 16 + bb) * LN + l] = acc;
    }
}

// ---------------------------------------------------------------------------
extern "C" void kernel_launch(void* const* d_in, const int* in_sizes, int n_in,
                              void* d_out, int out_size) {
    const float* y      = (const float*)d_in[0];
    const float* z      = (const float*)d_in[1];
    const float* u      = (const float*)d_in[2];
    const float* mu     = (const float*)d_in[3];
    const float* sig    = (const float*)d_in[4];
    const float* a_coef = (const float*)d_in[5];
    const float* b_coef = (const float*)d_in[6];
    const float* bias   = (const float*)d_in[7];
    float* out = (float*)d_out;

    const int qsmem = (DN * BT + KT * DN) * sizeof(float);  // 98304 B
    cudaFuncSetAttribute(quad_hybrid_kernel,
                         cudaFuncAttributeMaxDynamicSharedMemorySize, qsmem);

    quad_hybrid_kernel<<<dim3(64, 2, CN), 256, qsmem>>>(z, mu, sig);
    arx_out_kernel<<<BN / 16, 256>>>(y, u, a_coef, b_coef, bias, out);
}

// round 12
// speedup vs baseline: 1.4885x; 1.4885x over previous
#include <cuda_runtime.h>
#include <cuda_fp16.h>
#include <cstdint>

#define BN 8192
#define CN 16
#define DN 256
#define RN 64
#define EN 32
#define ORDN 16
#define LN 32

#define MT 128   // bodies per CTA
#define NH 128   // j-half per CTA
#define KC 32    // K chunk (two k16 mma tiles)

// Scratch (__device__ globals; every element written each launch)
__device__ float g_q2[BN * CN * 2];

// smem u32 layout (per CTA, 33280 B total):
//  Dhi [0,2048)  Dlo [2048,4096)        8 KB each
//  Bhi [4096,6208)  Blo [6208,8320)     8448 B each (33-u32-pair padded rows)
#define SM_DLO 2048
#define SM_BHI 4096
#define SM_BLO 6208
#define SM_U32 8320

__device__ __forceinline__ uint32_t pk_h2(float a, float b) {
    __half2 h = __floats2half2_rn(a, b);  // .x = low half = first arg
    return *reinterpret_cast<uint32_t*>(&h);
}

// mma m16n8k16 fp16 -> fp32 accum (sm_80+ baseline; valid on plain sm_100)
__device__ __forceinline__ void mma_f16(float* c, uint4 a, uint2 b) {
    asm volatile(
        "mma.sync.aligned.m16n8k16.row.col.f32.f16.f16.f32 "
        "{%0,%1,%2,%3}, {%4,%5,%6,%7}, {%8,%9}, {%0,%1,%2,%3};"
        : "+f"(c[0]), "+f"(c[1]), "+f"(c[2]), "+f"(c[3])
        : "r"(a.x), "r"(a.y), "r"(a.z), "r"(a.w), "r"(b.x), "r"(b.y));
}

// ---------------------------------------------------------------------------
// quad_mma_kernel: d2[b,c] over one j-half:
//   q[b,c,half] = sum_{j in half} ( sum_i sig[c,i,j] * (mu[c,i]-z[b,i]) )^2
// fp16x3 split (hh + hl + lh) on mma.sync m16n8k16.
// grid (BN/MT, 2, CN), 256 thr, 2 CTAs/SM, single-stage sync (round-9 pattern).
//
// m16n8k16 fragment maps (PTX ISA; g=lane>>2, t=lane&3):
//   A regs a0..a3: (row g|g+8, k-pair t | t+4): reg = rh + 2*sl
//   B regs b0,b1:  (k-pair t | t+4, col g):     reg = sl
//   C regs c0..c3: (row g, col 2t|2t+1), (row g+8, ...)
// ---------------------------------------------------------------------------
__global__ __launch_bounds__(256, 2) void quad_mma_kernel(
    const float* __restrict__ z, const float* __restrict__ mu,
    const float* __restrict__ sig) {
    extern __shared__ uint32_t smu[];
    const int btile = blockIdx.x, nh = blockIdx.y, c = blockIdx.z;
    const int b0 = btile * MT, j0 = nh * NH;
    const int tid = threadIdx.x, wid = tid >> 5, lane = tid & 31;

    float acc[16][4];
#pragma unroll
    for (int nt = 0; nt < 16; nt++)
#pragma unroll
        for (int i = 0; i < 4; i++) acc[nt][i] = 0.f;

    const float* sigc = sig + (size_t)c * DN * DN;
    __half* BhiH = (__half*)(smu + SM_BHI);
    __half* BloH = (__half*)(smu + SM_BLO);

    for (int kt = 0; kt < DN / KC; kt++) {
        const int i0 = kt * KC;
        if (kt) __syncthreads();  // previous chunk's reads complete

        // --- stage D (A operand): d = mu - z, fp16 hi/lo, fragment order ---
#pragma unroll
        for (int it = 0; it < 4; it++) {
            int idx = tid + it * 256;          // 0..1023
            int b = idx >> 3, i4 = idx & 7;
            float4 zv = *(const float4*)(z + (size_t)(b0 + b) * DN + i0 + i4 * 4);
            float4 m4 = *(const float4*)(mu + c * DN + i0 + i4 * 4);  // warp-uniform
            float v[4] = {m4.x - zv.x, m4.y - zv.y, m4.z - zv.z, m4.w - zv.w};
            __half h0 = __float2half_rn(v[0]), h1 = __float2half_rn(v[1]);
            __half h2 = __float2half_rn(v[2]), h3 = __float2half_rn(v[3]);
            float l0 = v[0] - __half2float(h0), l1 = v[1] - __half2float(h1);
            float l2 = v[2] - __half2float(h2), l3 = v[3] - __half2float(h3);
            int r = b & 15, g = r & 7, rh = r >> 3, mslot = b >> 4;
            int kt16 = i4 >> 2;
            int sl = (i4 >> 1) & 1;
            int t0 = (i4 & 1) * 2;             // first k-pair's t; second = t0+1
            int reg = rh + 2 * sl;
            int base = ((mslot * 2 + kt16) * 32 + g * 4 + t0) * 4 + reg;
            smu[base]              = pk_h2(__half2float(h0), __half2float(h1));
            smu[base + 4]          = pk_h2(__half2float(h2), __half2float(h3));
            smu[SM_DLO + base]     = pk_h2(l0, l1);
            smu[SM_DLO + base + 4] = pk_h2(l2, l3);
        }
        // --- stage B: sig K-major (k=i, n=j), fp16 hi/lo, padded rows (33) ---
#pragma unroll
        for (int it = 0; it < 4; it++) {
            int idx = tid + it * 256;          // 0..1023
            int ii = idx >> 5, j4 = idx & 31;  // coalesced 512B per warp
            float4 av = *(const float4*)(sigc + (size_t)(i0 + ii) * DN + j0 + j4 * 4);
            float v[4] = {av.x, av.y, av.z, av.w};
            int kk = ii & 15, kt16 = ii >> 4;
            int t = (kk & 7) >> 1, sl = kk >> 3, hp = kk & 1;
#pragma unroll
            for (int e = 0; e < 4; e++) {
                int jl = j4 * 4 + e;
                int nt = jl >> 3, g = jl & 7;
                // u32 idx = ((kt16*16+nt)*33 + g*4+t)*2 + sl ; halves at *2+hp
                int hidx = ((((kt16 * 16 + nt) * 33 + g * 4 + t) * 2 + sl) * 2) + hp;
                __half h = __float2half_rn(v[e]);
                BhiH[hidx] = h;
                BloH[hidx] = __float2half_rn(v[e] - __half2float(h));
            }
        }
        __syncthreads();

        // --- compute: 2 k16-tiles x 16 ntiles x {hh, hl, lh} ---
        const uint4* Dhi4 = (const uint4*)smu;              // 512 uint4
        const uint4* Dlo4 = (const uint4*)(smu + SM_DLO);
        const uint2* Bhi2 = (const uint2*)(smu + SM_BHI);   // padded rows of 33
        const uint2* Blo2 = (const uint2*)(smu + SM_BLO);
#pragma unroll
        for (int ktile = 0; ktile < 2; ktile++) {
            uint4 ah = Dhi4[(wid * 2 + ktile) * 32 + lane];
            uint4 al = Dlo4[(wid * 2 + ktile) * 32 + lane];
#pragma unroll
            for (int nt = 0; nt < 16; nt++) {
                uint2 bh = Bhi2[(ktile * 16 + nt) * 33 + lane];
                uint2 bl = Blo2[(ktile * 16 + nt) * 33 + lane];
                mma_f16(acc[nt], ah, bh);
                mma_f16(acc[nt], ah, bl);
                mma_f16(acc[nt], al, bh);
            }
        }
    }

    // Epilogue: q = sum_j acc^2 over this j-half (d already includes mu).
    float q0 = 0.f, q1 = 0.f;
#pragma unroll
    for (int nt = 0; nt < 16; nt++) {
        q0 += acc[nt][0] * acc[nt][0] + acc[nt][1] * acc[nt][1];
        q1 += acc[nt][2] * acc[nt][2] + acc[nt][3] * acc[nt][3];
    }
    q0 += __shfl_xor_sync(0xffffffffu, q0, 1);
    q0 += __shfl_xor_sync(0xffffffffu, q0, 2);
    q1 += __shfl_xor_sync(0xffffffffu, q1, 1);
    q1 += __shfl_xor_sync(0xffffffffu, q1, 2);
    if ((lane & 3) == 0) {
        int b = b0 + wid * 16 + (lane >> 2);
        g_q2[((size_t)b * CN + c) * 2 + nh]       = q0;
        g_q2[((size_t)(b + 8) * CN + c) * 2 + nh] = q1;
    }
}

// ---------------------------------------------------------------------------
// Kernel B: d2 -> softmax -> ARX recursion -> weighted output.
// ---------------------------------------------------------------------------
__global__ __launch_bounds__(256) void arx_out_kernel(
    const float* __restrict__ y, const float* __restrict__ u,
    const float* __restrict__ a_coef, const float* __restrict__ b_coef,
    const float* __restrict__ bias, float* __restrict__ out) {
    __shared__ float ps[16 * 16 * 33];
    __shared__ float acs[CN * ORDN];
    __shared__ float bcs[CN * EN];
    __shared__ float bss[CN];

    const int tid = threadIdx.x;
    if (tid < CN * ORDN) acs[tid] = a_coef[tid];
    for (int i = tid; i < CN * EN; i += 256) bcs[i] = b_coef[i];
    if (tid < CN) bss[tid] = bias[tid];
    __syncthreads();

    const int tb = tid >> 4;
    const int tc = tid & 15;
    const int b  = blockIdx.x * 16 + tb;

    float d2 = g_q2[((size_t)b * CN + tc) * 2] + g_q2[((size_t)b * CN + tc) * 2 + 1];
    d2 = fmaxf(d2, 1e-8f);

    float mn = d2;
#pragma unroll
    for (int m = 8; m; m >>= 1) mn = fminf(mn, __shfl_xor_sync(0xffffffffu, mn, m));
    float e = expf(-(d2 - mn));
    float ssum = e;
#pragma unroll
    for (int m = 8; m; m >>= 1) ssum += __shfl_xor_sync(0xffffffffu, ssum, m);
    float psi = e / ssum;

    const float4* uv = (const float4*)(u + ((size_t)b * CN + tc) * EN);
    float ub = bss[tc];
#pragma unroll
    for (int k = 0; k < EN / 4; k++) {
        float4 uu = uv[k];
        const float* bc = &bcs[tc * EN + k * 4];
        ub += uu.x * bc[0] + uu.y * bc[1] + uu.z * bc[2] + uu.w * bc[3];
    }

    float s[ORDN];
    const float4* yv = (const float4*)(y + ((size_t)b * CN + tc) * RN + (RN - ORDN));
#pragma unroll
    for (int k = 0; k < ORDN / 4; k++) {
        float4 t = yv[k];
        s[k * 4 + 0] = t.x; s[k * 4 + 1] = t.y;
        s[k * 4 + 2] = t.z; s[k * 4 + 3] = t.w;
    }
    float ar[ORDN];
#pragma unroll
    for (int o = 0; o < ORDN; o++) ar[o] = acs[tc * ORDN + o];

    float* myps = &ps[(tb * 16 + tc) * 33];
#pragma unroll
    for (int l = 0; l < LN; l++) {
        float y0 = 0.f, y1 = 0.f;
#pragma unroll
        for (int o = 0; o < ORDN; o += 2) {
            y0 += s[o] * ar[o];
            y1 += s[o + 1] * ar[o + 1];
        }
        float yn = ub + y0 + y1;
#pragma unroll
        for (int o = 0; o < ORDN - 1; o++) s[o] = s[o + 1];
        s[ORDN - 1] = yn;
        myps[l] = psi * yn;
    }
    __syncthreads();

    for (int o = tid; o < 16 * LN; o += 256) {
        int bb = o >> 5, l = o & 31;
        float acc = 0.f;
#pragma unroll
        for (int cc = 0; cc < CN; cc++) acc += ps[(bb * 16 + cc) * 33 + l];
        out[(size_t)(blockIdx.x * 16 + bb) * LN + l] = acc;
    }
}

// ---------------------------------------------------------------------------
extern "C" void kernel_launch(void* const* d_in, const int* in_sizes, int n_in,
                              void* d_out, int out_size) {
    const float* y      = (const float*)d_in[0];
    const float* z      = (const float*)d_in[1];
    const float* u      = (const float*)d_in[2];
    const float* mu     = (const float*)d_in[3];
    const float* sig    = (const float*)d_in[4];
    const float* a_coef = (const float*)d_in[5];
    const float* b_coef = (const float*)d_in[6];
    const float* bias   = (const float*)d_in[7];
    float* out = (float*)d_out;

    const int qsmem = SM_U32 * sizeof(uint32_t);  // 33280 B
    cudaFuncSetAttribute(quad_mma_kernel,
                         cudaFuncAttributeMaxDynamicSharedMemorySize, qsmem);

    quad_mma_kernel<<<dim3(BN / MT, 2, CN), 256, qsmem>>>(z, mu, sig);
    arx_out_kernel<<<BN / 16, 256>>>(y, u, a_coef, b_coef, bias, out);
}